// round 2
// baseline (speedup 1.0000x reference)
#include <cuda_runtime.h>
#include <math.h>

#define BATCH 8
#define NBOX  300
#define TOPK  20
#define HW    512
#define CROPS 64
#define OC    256
#define FCO   4096

// d_out layout (floats): Objects[8,20,4] | Object_features[8,20,4096] | valid[8,20] | fullframe[8,4096]
#define OBJ_OFF   0
#define FEAT_OFF  640
#define VALID_OFF 656000
#define FULL_OFF  656160

__constant__ float c_mean[3] = {0.485f, 0.456f, 0.406f};
__constant__ float c_istd[3] = {1.0f/0.229f, 1.0f/0.224f, 1.0f/0.225f};

// scratch (__device__ globals; no allocation allowed)
__device__ float g_pooled_full[BATCH*OC];
__device__ float g_pooled_crop[BATCH*TOPK*OC];
__device__ float g_crops[BATCH*TOPK*3*CROPS*CROPS];
__device__ float g_Wt[147*OC];          // transposed conv weights: [k][oc]
__device__ float g_job_box[BATCH*TOPK*4];
__device__ int   g_job_b[BATCH*TOPK];
__device__ int   g_job_bk[BATCH*TOPK];
__device__ int   g_njobs;
__device__ int   g_lab64;               // 1 if labels buffer is int64, 0 if int32

// ---------------------------------------------------------------- init
__global__ void init_kernel() {
    int i = blockIdx.x*blockDim.x + threadIdx.x;
    if (i < BATCH*OC)       g_pooled_full[i] = 0.f;
    if (i < BATCH*TOPK*OC)  g_pooled_crop[i] = 0.f;
    if (i == 0)             g_njobs = 0;
}

// probe labels dtype: read first 1200 int64 words (== full extent of an int32
// buffer of 2400 elems, so never OOB). Genuine int64 labels are all in [0,91);
// int32 data misread as int64 yields values >= 2^32 almost everywhere.
__global__ void lab_probe_kernel(const long long* __restrict__ lab) {
    __shared__ int bad;
    if (threadIdx.x == 0) bad = 0;
    __syncthreads();
    for (int i = threadIdx.x; i < 1200; i += blockDim.x) {
        long long v = lab[i];
        if (v < 0 || v >= 91) bad = 1;
    }
    __syncthreads();
    if (threadIdx.x == 0) g_lab64 = bad ? 0 : 1;
}

// transpose Wc [256][3*7*7] -> g_Wt [147][256]
__global__ void wtrans_kernel(const float* __restrict__ Wc) {
    int k = blockIdx.x;       // 0..146
    int c = threadIdx.x;      // 0..255
    g_Wt[k*OC + c] = Wc[c*147 + k];
}

// ---------------------------------------------------------------- top-k
__global__ void topk_kernel(const float* __restrict__ boxes,
                            const float* __restrict__ scores,
                            const void* __restrict__ labels_raw,
                            float* __restrict__ out) {
    int b = blockIdx.x;
    int t = threadIdx.x;
    __shared__ float sv[NBOX];
    __shared__ float rv[128];
    __shared__ int   ri[128];

    int lab64 = g_lab64;
    const int*       l32 = (const int*)labels_raw;
    const long long* l64 = (const long long*)labels_raw;

    for (int i = t; i < NBOX; i += 128) {
        long long l = lab64 ? l64[b*NBOX + i] : (long long)l32[b*NBOX + i];
        bool veh = (l==2)||(l==3)||(l==4)||(l==6)||(l==8);
        float s = scores[b*NBOX + i];
        sv[i] = (veh && s > 0.8f) ? s : -INFINITY;
    }
    __syncthreads();

    for (int k = 0; k < TOPK; k++) {
        float bv = -INFINITY; int bi = 0x7fffffff;
        for (int i = t; i < NBOX; i += 128) {
            float v = sv[i];
            if (v > bv || (v == bv && i < bi)) { bv = v; bi = i; }
        }
        rv[t] = bv; ri[t] = bi;
        __syncthreads();
        for (int s = 64; s > 0; s >>= 1) {
            if (t < s) {
                float ov = rv[t+s]; int oi = ri[t+s];
                if (ov > rv[t] || (ov == rv[t] && oi < ri[t])) { rv[t]=ov; ri[t]=oi; }
            }
            __syncthreads();
        }
        if (t == 0) {
            float bv0 = rv[0]; int bi0 = ri[0];
            bool valid = (bv0 != -INFINITY);
            float b0=0.f,b1=0.f,b2=0.f,b3=0.f;
            if (valid) {
                const float* bp = boxes + (b*NBOX + bi0)*4;
                b0=bp[0]; b1=bp[1]; b2=bp[2]; b3=bp[3];
                sv[bi0] = -INFINITY;
            }
            int bk = b*TOPK + k;
            out[OBJ_OFF + bk*4+0] = b0;
            out[OBJ_OFF + bk*4+1] = b1;
            out[OBJ_OFF + bk*4+2] = b2;
            out[OBJ_OFF + bk*4+3] = b3;
            out[VALID_OFF + bk]   = valid ? 1.0f : 0.0f;
            if (valid && b2 > b0 && b3 > b1) {   // non-degenerate
                int pos = atomicAdd(&g_njobs, 1);
                g_job_box[pos*4+0]=b0; g_job_box[pos*4+1]=b1;
                g_job_box[pos*4+2]=b2; g_job_box[pos*4+3]=b3;
                g_job_b[pos]  = b;
                g_job_bk[pos] = bk;
            }
        }
        __syncthreads();
    }
}

// ---------------------------------------------------------------- RoIAlign (normalized on the fly)
__global__ void sample_kernel(const float* __restrict__ x) {
    int j = blockIdx.x;
    if (j >= g_njobs) return;
    int b = g_job_b[j];
    float bx0 = g_job_box[j*4+0], by0 = g_job_box[j*4+1];
    float bx1 = g_job_box[j*4+2], by1 = g_job_box[j*4+3];
    for (int idx = threadIdx.x; idx < 3*CROPS*CROPS; idx += blockDim.x) {
        int c  = idx >> 12;
        int rem = idx & 4095;
        int yi = rem >> 6, xi = rem & 63;
        float ys = by0 + (yi + 0.5f)*(1.0f/CROPS)*(by1 - by0);
        float xs = bx0 + (xi + 0.5f)*(1.0f/CROPS)*(bx1 - bx0);
        float yf = floorf(ys), xf = floorf(xs);
        float wy = ys - yf,  wx = xs - xf;
        int y0 = min(max((int)yf, 0), HW-1); int y1 = min(y0+1, HW-1);
        int x0 = min(max((int)xf, 0), HW-1); int x1 = min(x0+1, HW-1);
        const float* img = x + ((long)b*3 + c)*HW*HW;
        float m = c_mean[c], is = c_istd[c];
        float Ia = (img[y0*HW + x0]-m)*is, Ib = (img[y0*HW + x1]-m)*is;
        float Ic = (img[y1*HW + x0]-m)*is, Id = (img[y1*HW + x1]-m)*is;
        g_crops[j*(3*CROPS*CROPS) + idx] =
            Ia*(1.f-wy)*(1.f-wx) + Ib*(1.f-wy)*wx + Ic*wy*(1.f-wx) + Id*wy*wx;
    }
}

// ---------------------------------------------------------------- fullframe conv+ReLU+pool
// block = (ch_tile ct, out_row oy, image b); 256 thr = 32 px-groups x 8 ch-groups
// patch smem: phase-decomposed [cin][ky][r=p&3][q=p>>2], plane stride 132 -> stride-1 LDS
__global__ void __launch_bounds__(256) conv_full_kernel(const float* __restrict__ x,
                                                        const float* __restrict__ bc) {
    int ct = blockIdx.x, oy = blockIdx.y, b = blockIdx.z;
    int c0 = ct*64;
    extern __shared__ float sm[];
    float* smP = sm;            // 3*7*528 = 11088
    float* smW = sm + 11088;    // 147*64  = 9408
    int t = threadIdx.x;

    for (int s = t; s < 11088; s += 256) smP[s] = 0.f;
    __syncthreads();
    int iyb = oy*4 - 1;
    for (int s = t; s < 3*7*516; s += 256) {
        int plane = s / 516; int p = s - plane*516;
        int cin = plane / 7, ky = plane - cin*7;
        int iy = iyb + ky;  int ix = p - 1;
        float v = 0.f;
        if ((unsigned)iy < 512u && (unsigned)ix < 512u)
            v = (x[(((long)b*3 + cin)*512 + iy)*512 + ix] - c_mean[cin]) * c_istd[cin];
        smP[plane*528 + (p&3)*132 + (p>>2)] = v;
    }
    for (int s = t; s < 147*64; s += 256) {
        int k = s >> 6, c = s & 63;
        smW[s] = g_Wt[k*OC + c0 + c];
    }
    __syncthreads();

    int pg = t & 31, cg = t >> 5;
    float acc[4][8];
    #pragma unroll
    for (int i = 0; i < 8; i++) {
        float bv = bc[c0 + cg*8 + i];
        acc[0][i]=bv; acc[1][i]=bv; acc[2][i]=bv; acc[3][i]=bv;
    }
    for (int cin = 0; cin < 3; cin++) {
        #pragma unroll
        for (int ky = 0; ky < 7; ky++) {
            const float* pl = smP + (cin*7 + ky)*528 + pg;
            const float* wk = smW + (cin*7 + ky)*7*64 + cg*8;
            #pragma unroll
            for (int kx = 0; kx < 7; kx++) {
                int off = (kx & 3)*132 + (kx >> 2);
                float a0 = pl[off], a1 = pl[off+32], a2 = pl[off+64], a3 = pl[off+96];
                float4 wA = *(const float4*)(wk + kx*64);
                float4 wB = *(const float4*)(wk + kx*64 + 4);
                float w[8] = {wA.x,wA.y,wA.z,wA.w,wB.x,wB.y,wB.z,wB.w};
                #pragma unroll
                for (int i = 0; i < 8; i++) {
                    acc[0][i] += a0*w[i];
                    acc[1][i] += a1*w[i];
                    acc[2][i] += a2*w[i];
                    acc[3][i] += a3*w[i];
                }
            }
        }
    }
    #pragma unroll
    for (int i = 0; i < 8; i++) {
        float s = fmaxf(acc[0][i],0.f)+fmaxf(acc[1][i],0.f)
                + fmaxf(acc[2][i],0.f)+fmaxf(acc[3][i],0.f);
        #pragma unroll
        for (int o = 16; o > 0; o >>= 1) s += __shfl_down_sync(0xffffffffu, s, o);
        if (pg == 0) atomicAdd(&g_pooled_full[b*OC + c0 + cg*8 + i], s);
    }
}

// ---------------------------------------------------------------- crop conv+ReLU+pool (only real jobs)
__global__ void __launch_bounds__(256) conv_crop_kernel(const float* __restrict__ bc) {
    int ct = blockIdx.x, j = blockIdx.y;
    if (j >= g_njobs) return;
    int c0 = ct*64;
    extern __shared__ float sm[];
    float* smP = sm;            // 3*67*80 = 16080
    float* smW = sm + 16080;    // 9408
    int t = threadIdx.x;

    for (int s = t; s < 16080; s += 256) smP[s] = 0.f;
    __syncthreads();
    const float* crop = g_crops + (long)j*(3*CROPS*CROPS);
    for (int s = t; s < 3*67*67; s += 256) {
        int row = s / 67; int p = s - row*67;
        int cin = row / 67;
        int iy = row - cin*67;
        int cy = iy - 1, cx = p - 1;
        float v = 0.f;
        if ((unsigned)cy < 64u && (unsigned)cx < 64u)
            v = crop[(cin*64 + cy)*64 + cx];
        smP[row*80 + (p&3)*20 + (p>>2)] = v;
    }
    for (int s = t; s < 147*64; s += 256) {
        int k = s >> 6, c = s & 63;
        smW[s] = g_Wt[k*OC + c0 + c];
    }
    __syncthreads();

    int pg = t & 31, cg = t >> 5;
    float bcv[8];
    #pragma unroll
    for (int i = 0; i < 8; i++) bcv[i] = bc[c0 + cg*8 + i];
    float pool[8] = {0.f,0.f,0.f,0.f,0.f,0.f,0.f,0.f};

    for (int pass = 0; pass < 2; pass++) {
        float acc[4][8];
        #pragma unroll
        for (int i = 0; i < 8; i++) { acc[0][i]=bcv[i]; acc[1][i]=bcv[i]; acc[2][i]=bcv[i]; acc[3][i]=bcv[i]; }
        int oyv[4], oxv[4];
        #pragma unroll
        for (int jj = 0; jj < 4; jj++) {
            int px = pass*128 + pg + 32*jj;
            oyv[jj] = px >> 4; oxv[jj] = px & 15;
        }
        for (int cin = 0; cin < 3; cin++) {
            #pragma unroll
            for (int ky = 0; ky < 7; ky++) {
                int rb[4];
                #pragma unroll
                for (int jj = 0; jj < 4; jj++)
                    rb[jj] = (cin*67 + oyv[jj]*4 + ky)*80 + oxv[jj];
                const float* wk = smW + (cin*7 + ky)*7*64 + cg*8;
                #pragma unroll
                for (int kx = 0; kx < 7; kx++) {
                    int off = (kx & 3)*20 + (kx >> 2);
                    float a0 = smP[rb[0]+off], a1 = smP[rb[1]+off];
                    float a2 = smP[rb[2]+off], a3 = smP[rb[3]+off];
                    float4 wA = *(const float4*)(wk + kx*64);
                    float4 wB = *(const float4*)(wk + kx*64 + 4);
                    float w[8] = {wA.x,wA.y,wA.z,wA.w,wB.x,wB.y,wB.z,wB.w};
                    #pragma unroll
                    for (int i = 0; i < 8; i++) {
                        acc[0][i] += a0*w[i];
                        acc[1][i] += a1*w[i];
                        acc[2][i] += a2*w[i];
                        acc[3][i] += a3*w[i];
                    }
                }
            }
        }
        #pragma unroll
        for (int i = 0; i < 8; i++)
            pool[i] += fmaxf(acc[0][i],0.f)+fmaxf(acc[1][i],0.f)
                     + fmaxf(acc[2][i],0.f)+fmaxf(acc[3][i],0.f);
    }
    #pragma unroll
    for (int i = 0; i < 8; i++) {
        float s = pool[i];
        #pragma unroll
        for (int o = 16; o > 0; o >>= 1) s += __shfl_down_sync(0xffffffffu, s, o);
        if (pg == 0) atomicAdd(&g_pooled_crop[j*OC + c0 + cg*8 + i], s);
    }
}

// ---------------------------------------------------------------- FC fullframe
__global__ void fc_full_kernel(const float* __restrict__ Wf,
                               const float* __restrict__ bf,
                               float* __restrict__ out) {
    __shared__ float sp[BATCH*OC];
    int t = threadIdx.x;
    for (int s = t; s < BATCH*OC; s += 256)
        sp[s] = g_pooled_full[s] * (1.0f/16384.0f);
    __syncthreads();
    int o = blockIdx.x*256 + t;
    float acc[8] = {0.f,0.f,0.f,0.f,0.f,0.f,0.f,0.f};
    for (int c = 0; c < OC; c++) {
        float w = Wf[(long)c*FCO + o];
        #pragma unroll
        for (int b2 = 0; b2 < 8; b2++) acc[b2] += sp[b2*OC + c] * w;
    }
    float bias = bf[o];
    #pragma unroll
    for (int b2 = 0; b2 < 8; b2++)
        out[FULL_OFF + b2*FCO + o] = acc[b2] + bias;
}

// ---------------------------------------------------------------- FC crops (jobs only; rest pre-zeroed)
__global__ void fc_crop_kernel(const float* __restrict__ Wf,
                               const float* __restrict__ bf,
                               float* __restrict__ out) {
    int j0 = blockIdx.y*8;
    int nj = g_njobs;
    if (j0 >= nj) return;
    __shared__ float sp[8*OC];
    int t = threadIdx.x;
    for (int s = t; s < 8*OC; s += 256) {
        int jj = s >> 8; int c = s & 255;
        int j = j0 + jj;
        sp[s] = (j < nj) ? g_pooled_crop[j*OC + c] * (1.0f/256.0f) : 0.f;
    }
    __syncthreads();
    int o = blockIdx.x*256 + t;
    float acc[8] = {0.f,0.f,0.f,0.f,0.f,0.f,0.f,0.f};
    for (int c = 0; c < OC; c++) {
        float w = Wf[(long)c*FCO + o];
        #pragma unroll
        for (int jj = 0; jj < 8; jj++) acc[jj] += sp[jj*OC + c] * w;
    }
    float bias = bf[o];
    #pragma unroll
    for (int jj = 0; jj < 8; jj++) {
        int j = j0 + jj;
        if (j < nj)
            out[FEAT_OFF + (long)g_job_bk[j]*FCO + o] = acc[jj] + bias;
    }
}

// ---------------------------------------------------------------- launch
extern "C" void kernel_launch(void* const* d_in, const int* in_sizes, int n_in,
                              void* d_out, int out_size) {
    const float*     x      = (const float*)d_in[0];
    const float*     boxes  = (const float*)d_in[1];
    const float*     scores = (const float*)d_in[2];
    const void*      labels = d_in[3];
    const float*     Wc     = (const float*)d_in[4];
    const float*     bc     = (const float*)d_in[5];
    const float*     Wf     = (const float*)d_in[6];
    const float*     bf     = (const float*)d_in[7];
    float* out = (float*)d_out;

    cudaFuncSetAttribute(conv_full_kernel, cudaFuncAttributeMaxDynamicSharedMemorySize, 81984);
    cudaFuncSetAttribute(conv_crop_kernel, cudaFuncAttributeMaxDynamicSharedMemorySize, 101952);

    init_kernel<<<160, 256>>>();
    lab_probe_kernel<<<1, 256>>>((const long long*)labels);
    wtrans_kernel<<<147, 256>>>(Wc);
    topk_kernel<<<BATCH, 128>>>(boxes, scores, labels, out);
    cudaMemsetAsync(out + FEAT_OFF, 0, (size_t)BATCH*TOPK*FCO*sizeof(float));
    sample_kernel<<<BATCH*TOPK, 256>>>(x);
    conv_full_kernel<<<dim3(4, 128, BATCH), 256, 81984>>>(x, bc);
    conv_crop_kernel<<<dim3(4, BATCH*TOPK), 256, 101952>>>(bc);
    fc_full_kernel<<<16, 256>>>(Wf, bf, out);
    fc_crop_kernel<<<dim3(16, 20), 256>>>(Wf, bf, out);
}